// round 11
// baseline (speedup 1.0000x reference)
#include <cuda_runtime.h>
#include <cuda_fp16.h>
#include <cstdint>

#define N_NODES 50000
#define N_EDGES 800000
#define IN_C 256
#define HID_C 256
#define OUT_C 128
#define NB_SCAN ((N_NODES + 255) / 256)
#define CHUNK0 25088                     // 196 blocks of 128 rows

// ---------------- scratch (static device globals; no runtime alloc) ----------
__device__ __align__(256) __half g_h1[N_NODES * HID_C];
__device__ __align__(256) __half g_a1[N_NODES * HID_C];
__device__ __align__(256) __half g_h2[N_NODES * OUT_C];
__device__ __align__(256) __half g_W1h[HID_C * IN_C];    // W1^T fp16 [N=256][K=256]
__device__ __align__(256) __half g_W2h[OUT_C * HID_C];   // W2^T fp16 [N=128][K=256]
__device__ int2  g_csrw[N_EDGES];        // (src, fp32 bits of dinv[src]) by dst
__device__ int   g_ptr[N_NODES + 1];
__device__ int   g_cnt[N_NODES];
__device__ int   g_cur[N_NODES];
__device__ float g_dinv[N_NODES];
__device__ int   g_bsum[256];
__device__ int   g_is64;

// ---------------- one-time stream/event infra --------------------------------
struct StreamInit {
    cudaStream_t s2;
    cudaEvent_t evF, evJ, evG1, evB;
    StreamInit() {
        cudaStreamCreate(&s2);
        cudaEventCreateWithFlags(&evF, cudaEventDisableTiming);
        cudaEventCreateWithFlags(&evJ, cudaEventDisableTiming);
        cudaEventCreateWithFlags(&evG1, cudaEventDisableTiming);
        cudaEventCreateWithFlags(&evB, cudaEventDisableTiming);
    }
};
static StreamInit g_si;

// ---------------- prep: zero + dtype detect + W2 transpose (fused) -----------
// blocks [0, NB_SCAN): zero cnt/cur (+ block 0 detects edge dtype)
// blocks [NB_SCAN, NB_SCAN+32): transpose+convert W2 -> W2T fp16 [N][K]
__global__ void prep_kernel(const unsigned int* __restrict__ w,
                            const float* __restrict__ W2,
                            __half* __restrict__ W2T) {
    __shared__ float tbuf[32][33];
    __shared__ int nz;
    int bid = blockIdx.x;
    if (bid < NB_SCAN) {
        int i = bid * 256 + threadIdx.x;
        if (i < N_NODES) { g_cnt[i] = 0; g_cur[i] = 0; }
        if (i == 0) g_ptr[N_NODES] = N_EDGES;
        if (bid == 0) {
            if (threadIdx.x == 0) nz = 0;
            __syncthreads();
            int bad = 0;
            for (int k = threadIdx.x; k < 4096; k += blockDim.x)
                if (w[2 * k + 1] != 0u) bad = 1;
            if (bad) atomicOr(&nz, 1);
            __syncthreads();
            if (threadIdx.x == 0) g_is64 = (nz == 0) ? 1 : 0;
        }
    } else {
        int tb = bid - NB_SCAN;          // 0..31
        int bx = (tb & 3) * 32;          // over OUT_C (=Nd) / 32 = 4
        int by = (tb >> 2) * 32;         // over HID_C (=Kd) / 32 = 8
        int x = threadIdx.x & 31, y = threadIdx.x >> 5;   // y: 0..7
#pragma unroll
        for (int j = 0; j < 32; j += 8)
            tbuf[y + j][x] = W2[(size_t)(by + y + j) * OUT_C + bx + x];
        __syncthreads();
#pragma unroll
        for (int j = 0; j < 32; j += 8)
            W2T[(size_t)(bx + y + j) * HID_C + by + x] = __float2half(tbuf[x][y + j]);
    }
}

__device__ __forceinline__ int edge_at(const void* ei, long long idx) {
    if (g_is64) return (int)((const long long*)ei)[idx];
    return ((const int*)ei)[idx];
}

// ---------------- CSR build --------------------------------------------------
__global__ void count_kernel(const void* __restrict__ ei) {
    int e = blockIdx.x * blockDim.x + threadIdx.x;
    if (e >= N_EDGES) return;
    int c = edge_at(ei, (long long)N_EDGES + e);
    atomicAdd(&g_cnt[c], 1);
}

__global__ void scan1_kernel() {
    int i = blockIdx.x * 256 + threadIdx.x;
    int v = (i < N_NODES) ? g_cnt[i] : 0;
    int lane = threadIdx.x & 31, w = threadIdx.x >> 5;
    for (int o = 16; o; o >>= 1) v += __shfl_down_sync(~0u, v, o);
    __shared__ int ws[8];
    if (!lane) ws[w] = v;
    __syncthreads();
    if (threadIdx.x == 0) {
        int s = 0;
        for (int k = 0; k < 8; k++) s += ws[k];
        g_bsum[blockIdx.x] = s;
    }
}

// merged scan2+scan3: each block computes its global offset as a masked
// reduction over g_bsum (sum of bsum[j], j < blockIdx), then does its local
// exclusive scan of g_cnt and writes g_ptr / g_dinv.
__global__ void scan3m_kernel() {
    int t = threadIdx.x, bid = blockIdx.x;
    int lane = t & 31, w = t >> 5;

    // block offset = sum_{j < bid} bsum[j]
    int v = (t < NB_SCAN && t < bid) ? g_bsum[t] : 0;
    for (int o = 16; o; o >>= 1) v += __shfl_down_sync(~0u, v, o);
    __shared__ int ws[8];
    __shared__ int boff;
    if (!lane) ws[w] = v;
    __syncthreads();
    if (t == 0) {
        int s = 0;
        for (int k = 0; k < 8; k++) s += ws[k];
        boff = s;
    }
    __syncthreads();

    // local exclusive scan
    int i = bid * 256 + t;
    int c = (i < N_NODES) ? g_cnt[i] : 0;
    int x = c;
    for (int o = 1; o < 32; o <<= 1) {
        int y = __shfl_up_sync(~0u, x, o);
        if (lane >= o) x += y;
    }
    __shared__ int ws2[8], wo[8];
    if (lane == 31) ws2[w] = x;
    __syncthreads();
    if (t == 0) {
        int r = 0;
        for (int k = 0; k < 8; k++) { wo[k] = r; r += ws2[k]; }
    }
    __syncthreads();
    if (i < N_NODES) {
        g_ptr[i] = boff + wo[w] + x - c;
        g_dinv[i] = rsqrtf((float)(c + 1));
    }
}

__global__ void fill_kernel(const void* __restrict__ ei) {
    int e = blockIdx.x * blockDim.x + threadIdx.x;
    if (e >= N_EDGES) return;
    int r = edge_at(ei, e);
    int c = edge_at(ei, (long long)N_EDGES + e);
    int pos = g_ptr[c] + atomicAdd(&g_cur[c], 1);
    g_csrw[pos] = make_int2(r, __float_as_int(g_dinv[r]));
}

// ---------------- W1 transpose+convert ----------------------------------------
__global__ void transpose_h_kernel(const float* __restrict__ W, __half* __restrict__ WT,
                                   int Kd, int Nd) {
    __shared__ float t[32][33];
    int bx = blockIdx.x * 32, by = blockIdx.y * 32;
    int x = threadIdx.x, y = threadIdx.y;
#pragma unroll
    for (int j = 0; j < 32; j += 8)
        t[y + j][x] = W[(size_t)(by + y + j) * Nd + bx + x];
    __syncthreads();
#pragma unroll
    for (int j = 0; j < 32; j += 8)
        WT[(size_t)(bx + y + j) * Kd + by + x] = __float2half(t[x][y + j]);
}

// ---------------- FP16 mma GEMM: C[M,N] = A[M,K] @ Bt[N,K]^T ------------------
// BM=128, BN=64, BK=32. 8 warps as 4(M) x 2(N); warp tile 32x32.
// Register prefetch + ping-pong SMEM (one __syncthreads per k-iter).
#define BM 128
#define BN 64
#define BK 32

__device__ __forceinline__ void mma_f16(float* c, const uint32_t* a, const uint32_t* b) {
    asm volatile(
        "mma.sync.aligned.m16n8k16.row.col.f32.f16.f16.f32 "
        "{%0,%1,%2,%3}, {%4,%5,%6,%7}, {%8,%9}, {%0,%1,%2,%3};"
        : "+f"(c[0]), "+f"(c[1]), "+f"(c[2]), "+f"(c[3])
        : "r"(a[0]), "r"(a[1]), "r"(a[2]), "r"(a[3]), "r"(b[0]), "r"(b[1]));
}

template <typename TA>
__global__ __launch_bounds__(256) void mma_hgemm_kernel(
    const TA* __restrict__ A, const __half* __restrict__ Bt,
    __half* __restrict__ C, int M, int N, int K)
{
    __shared__ __align__(16) __half As[2][BM][BK + 8];
    __shared__ __align__(16) __half Bs[2][BN][BK + 8];

    int tid = threadIdx.x;
    int lane = tid & 31, wid = tid >> 5;
    int wm = (wid & 3) * 32;
    int wn = (wid >> 2) * 32;
    int m0 = blockIdx.x * BM, n0 = blockIdx.y * BN;
    int g = lane >> 2, tq = lane & 3;

    float acc[2][4][4];
#pragma unroll
    for (int mt = 0; mt < 2; mt++)
#pragma unroll
        for (int nt = 0; nt < 4; nt++)
#pragma unroll
            for (int j = 0; j < 4; j++) acc[mt][nt][j] = 0.0f;

    float4 pa_f[4];
    uint4  pa_h[2];
    uint4  pb;

    auto load_tile = [&](int k0) {
        if constexpr (sizeof(TA) == 4) {
#pragma unroll
            for (int i = 0; i < 4; i++) {
                int slot = tid + 256 * i;
                int m = slot >> 3, c4 = slot & 7;
                pa_f[i] = make_float4(0.f, 0.f, 0.f, 0.f);
                if (m0 + m < M)
                    pa_f[i] = *(const float4*)((const float*)A +
                                               (size_t)(m0 + m) * K + k0 + c4 * 4);
            }
        } else {
#pragma unroll
            for (int i = 0; i < 2; i++) {
                int slot = tid + 256 * i;
                int m = slot >> 2, c8 = slot & 3;
                pa_h[i] = make_uint4(0u, 0u, 0u, 0u);
                if (m0 + m < M)
                    pa_h[i] = *(const uint4*)((const __half*)A +
                                              (size_t)(m0 + m) * K + k0 + c8 * 8);
            }
        }
        {
            int n = tid >> 2, c8 = tid & 3;
            pb = *(const uint4*)(Bt + (size_t)(n0 + n) * K + k0 + c8 * 8);
        }
    };

    auto store_tile = [&](int b) {
        if constexpr (sizeof(TA) == 4) {
#pragma unroll
            for (int i = 0; i < 4; i++) {
                int slot = tid + 256 * i;
                int m = slot >> 3, c4 = slot & 7;
                uint2 u;
                ((__half2*)&u)[0] = __floats2half2_rn(pa_f[i].x, pa_f[i].y);
                ((__half2*)&u)[1] = __floats2half2_rn(pa_f[i].z, pa_f[i].w);
                *(uint2*)&As[b][m][c4 * 4] = u;
            }
        } else {
#pragma unroll
            for (int i = 0; i < 2; i++) {
                int slot = tid + 256 * i;
                int m = slot >> 2, c8 = slot & 3;
                *(uint4*)&As[b][m][c8 * 8] = pa_h[i];
            }
        }
        {
            int n = tid >> 2, c8 = tid & 3;
            *(uint4*)&Bs[b][n][c8 * 8] = pb;
        }
    };

    load_tile(0);
    const int NITER = K / BK;
    for (int it = 0; it < NITER; it++) {
        int b = it & 1;
        store_tile(b);
        __syncthreads();
        if (it + 1 < NITER) load_tile((it + 1) * BK);

#pragma unroll
        for (int kk = 0; kk < BK; kk += 16) {
            uint32_t a[2][4], bb[4][2];
#pragma unroll
            for (int mt = 0; mt < 2; mt++) {
                int r = wm + mt * 16 + g;
                a[mt][0] = *(const uint32_t*)&As[b][r][kk + 2 * tq];
                a[mt][1] = *(const uint32_t*)&As[b][r + 8][kk + 2 * tq];
                a[mt][2] = *(const uint32_t*)&As[b][r][kk + 2 * tq + 8];
                a[mt][3] = *(const uint32_t*)&As[b][r + 8][kk + 2 * tq + 8];
            }
#pragma unroll
            for (int nt = 0; nt < 4; nt++) {
                int n = wn + nt * 8 + g;
                bb[nt][0] = *(const uint32_t*)&Bs[b][n][kk + 2 * tq];
                bb[nt][1] = *(const uint32_t*)&Bs[b][n][kk + 2 * tq + 8];
            }
#pragma unroll
            for (int mt = 0; mt < 2; mt++)
#pragma unroll
                for (int nt = 0; nt < 4; nt++)
                    mma_f16(acc[mt][nt], a[mt], bb[nt]);
        }
        // no trailing sync: next store targets the other buffer, whose last
        // readers finished before they passed this iteration's sync.
    }

#pragma unroll
    for (int mt = 0; mt < 2; mt++) {
        int row = m0 + wm + mt * 16 + g;
#pragma unroll
        for (int nt = 0; nt < 4; nt++) {
            int col = n0 + wn + nt * 8 + tq * 2;
            if (row < M)
                *(__half2*)(C + (size_t)row * N + col) =
                    __floats2half2_rn(acc[mt][nt][0], acc[mt][nt][1]);
            if (row + 8 < M)
                *(__half2*)(C + (size_t)(row + 8) * N + col) =
                    __floats2half2_rn(acc[mt][nt][2], acc[mt][nt][3]);
        }
    }
}

// ---------------- aggregation (fp16 features, fp32 accumulate) ---------------
__device__ __forceinline__ void h8_fma(float w, uint4 v, float* acc) {
    const __half2* hp = (const __half2*)&v;
#pragma unroll
    for (int i = 0; i < 4; i++) {
        float2 f = __half22float2(hp[i]);
        acc[2 * i]     += w * f.x;
        acc[2 * i + 1] += w * f.y;
    }
}

__global__ __launch_bounds__(256) void agg256_kernel(
    const __half* __restrict__ h, __half* __restrict__ out,
    const float* __restrict__ bias, int node_base, int node_count)
{
    int warp = (blockIdx.x * blockDim.x + threadIdx.x) >> 5;
    int lane = threadIdx.x & 31;
    if (warp >= node_count) return;
    int node = node_base + warp;

    const uint4* hv = (const uint4*)h;
    int p0 = g_ptr[node], p1 = g_ptr[node + 1];
    float dc = g_dinv[node];

    float acc[8];
#pragma unroll
    for (int j = 0; j < 8; j++) acc[j] = 0.0f;
    h8_fma(dc, hv[(size_t)node * 32 + lane], acc);

    int e = p0;
    for (; e + 8 <= p1; e += 8) {
        int2 cc[8];
#pragma unroll
        for (int j = 0; j < 8; j++) cc[j] = g_csrw[e + j];
        uint4 vv[8];
#pragma unroll
        for (int j = 0; j < 8; j++) vv[j] = hv[(size_t)cc[j].x * 32 + lane];
#pragma unroll
        for (int j = 0; j < 8; j++) h8_fma(__int_as_float(cc[j].y), vv[j], acc);
    }
    for (; e + 2 <= p1; e += 2) {
        int2 c0 = g_csrw[e], c1 = g_csrw[e + 1];
        uint4 v0 = hv[(size_t)c0.x * 32 + lane];
        uint4 v1 = hv[(size_t)c1.x * 32 + lane];
        h8_fma(__int_as_float(c0.y), v0, acc);
        h8_fma(__int_as_float(c1.y), v1, acc);
    }
    if (e < p1) {
        int2 c0 = g_csrw[e];
        h8_fma(__int_as_float(c0.y), hv[(size_t)c0.x * 32 + lane], acc);
    }

    float4 b0 = ((const float4*)bias)[lane * 2];
    float4 b1 = ((const float4*)bias)[lane * 2 + 1];
    float r[8];
    r[0] = fmaxf(dc * acc[0] + b0.x, 0.f);
    r[1] = fmaxf(dc * acc[1] + b0.y, 0.f);
    r[2] = fmaxf(dc * acc[2] + b0.z, 0.f);
    r[3] = fmaxf(dc * acc[3] + b0.w, 0.f);
    r[4] = fmaxf(dc * acc[4] + b1.x, 0.f);
    r[5] = fmaxf(dc * acc[5] + b1.y, 0.f);
    r[6] = fmaxf(dc * acc[6] + b1.z, 0.f);
    r[7] = fmaxf(dc * acc[7] + b1.w, 0.f);

    uint4 o;
    __half2* op = (__half2*)&o;
    op[0] = __floats2half2_rn(r[0], r[1]);
    op[1] = __floats2half2_rn(r[2], r[3]);
    op[2] = __floats2half2_rn(r[4], r[5]);
    op[3] = __floats2half2_rn(r[6], r[7]);
    ((uint4*)out)[(size_t)node * 32 + lane] = o;
}

__global__ __launch_bounds__(256) void agg128_kernel(
    const __half* __restrict__ h, float* __restrict__ out,
    const float* __restrict__ bias)
{
    int gwarp = (blockIdx.x * blockDim.x + threadIdx.x) >> 5;
    int lane = threadIdx.x & 31;
    int node = gwarp * 2 + (lane >> 4);
    int l16 = lane & 15;
    if (node >= N_NODES) return;

    const uint4* hv = (const uint4*)h;
    int p0 = g_ptr[node], p1 = g_ptr[node + 1];
    float dc = g_dinv[node];

    float acc[8];
#pragma unroll
    for (int j = 0; j < 8; j++) acc[j] = 0.0f;
    h8_fma(dc, hv[(size_t)node * 16 + l16], acc);

    int e = p0;
    for (; e + 8 <= p1; e += 8) {
        int2 cc[8];
#pragma unroll
        for (int j = 0; j < 8; j++) cc[j] = g_csrw[e + j];
        uint4 vv[8];
#pragma unroll
        for (int j = 0; j < 8; j++) vv[j] = hv[(size_t)cc[j].x * 16 + l16];
#pragma unroll
        for (int j = 0; j < 8; j++) h8_fma(__int_as_float(cc[j].y), vv[j], acc);
    }
    for (; e + 2 <= p1; e += 2) {
        int2 c0 = g_csrw[e], c1 = g_csrw[e + 1];
        uint4 v0 = hv[(size_t)c0.x * 16 + l16];
        uint4 v1 = hv[(size_t)c1.x * 16 + l16];
        h8_fma(__int_as_float(c0.y), v0, acc);
        h8_fma(__int_as_float(c1.y), v1, acc);
    }
    if (e < p1) {
        int2 c0 = g_csrw[e];
        h8_fma(__int_as_float(c0.y), hv[(size_t)c0.x * 16 + l16], acc);
    }

    float4 b0 = ((const float4*)bias)[l16 * 2];
    float4 b1 = ((const float4*)bias)[l16 * 2 + 1];
    float4 o0, o1;
    o0.x = dc * acc[0] + b0.x;
    o0.y = dc * acc[1] + b0.y;
    o0.z = dc * acc[2] + b0.z;
    o0.w = dc * acc[3] + b0.w;
    o1.x = dc * acc[4] + b1.x;
    o1.y = dc * acc[5] + b1.y;
    o1.z = dc * acc[6] + b1.z;
    o1.w = dc * acc[7] + b1.w;

    float4* ov = (float4*)(out + (size_t)node * 128 + l16 * 8);
    ov[0] = o0;
    ov[1] = o1;
}

// ---------------- launch ------------------------------------------------------
extern "C" void kernel_launch(void* const* d_in, const int* in_sizes, int n_in,
                              void* d_out, int out_size)
{
    const float* x  = (const float*)d_in[0];
    const void*  ei = d_in[1];
    const float* W1 = (const float*)d_in[2];
    const float* b1 = (const float*)d_in[3];
    const float* W2 = (const float*)d_in[4];
    const float* b2 = (const float*)d_in[5];
    float* out = (float*)d_out;

    __half* h1;  cudaGetSymbolAddress((void**)&h1, g_h1);
    __half* a1;  cudaGetSymbolAddress((void**)&a1, g_a1);
    __half* h2;  cudaGetSymbolAddress((void**)&h2, g_h2);
    __half* w1h; cudaGetSymbolAddress((void**)&w1h, g_W1h);
    __half* w2h; cudaGetSymbolAddress((void**)&w2h, g_W2h);

    cudaStream_t s0 = 0, s2 = g_si.s2;

    // ---- fork ----
    cudaEventRecord(g_si.evF, s0);
    cudaStreamWaitEvent(s2, g_si.evF, 0);

    // branch A (s2): fused prep (zero+detect+W2T) + CSR build (5 launches)
    prep_kernel<<<NB_SCAN + 32, 256, 0, s2>>>((const unsigned int*)ei, W2, w2h);
    count_kernel<<<(N_EDGES + 255) / 256, 256, 0, s2>>>(ei);
    scan1_kernel<<<NB_SCAN, 256, 0, s2>>>();
    scan3m_kernel<<<NB_SCAN, 256, 0, s2>>>();
    fill_kernel<<<(N_EDGES + 255) / 256, 256, 0, s2>>>(ei);
    cudaEventRecord(g_si.evJ, s2);

    // branch B (s0): W1 prep + GEMM1 (fp16)
    transpose_h_kernel<<<dim3(HID_C / 32, IN_C / 32), dim3(32, 8), 0, s0>>>(
        W1, w1h, IN_C, HID_C);
    int grid_m = (N_NODES + BM - 1) / BM;   // 391
    mma_hgemm_kernel<float><<<dim3(grid_m, HID_C / BN), 256, 0, s0>>>(
        x, w1h, h1, N_NODES, HID_C, IN_C);
    cudaEventRecord(g_si.evG1, s0);

    // ---- pipelined layer-1 agg + layer-2 GEMM in two row chunks ----
    const int c1n = N_NODES - CHUNK0;                 // 24912
    // s0: chunk0
    cudaStreamWaitEvent(s0, g_si.evJ, 0);
    agg256_kernel<<<(CHUNK0 * 32 + 255) / 256, 256, 0, s0>>>(h1, a1, b1, 0, CHUNK0);
    mma_hgemm_kernel<__half><<<dim3(CHUNK0 / BM, OUT_C / BN), 256, 0, s0>>>(
        a1, w2h, h2, CHUNK0, OUT_C, HID_C);
    // s2: chunk1
    cudaStreamWaitEvent(s2, g_si.evG1, 0);
    agg256_kernel<<<(c1n * 32 + 255) / 256, 256, 0, s2>>>(h1, a1, b1, CHUNK0, c1n);
    mma_hgemm_kernel<__half><<<dim3((c1n + BM - 1) / BM, OUT_C / BN), 256, 0, s2>>>(
        a1 + (size_t)CHUNK0 * HID_C, w2h, h2 + (size_t)CHUNK0 * OUT_C,
        c1n, OUT_C, HID_C);
    cudaEventRecord(g_si.evB, s2);

    // ---- join + final aggregation ----
    cudaStreamWaitEvent(s0, g_si.evB, 0);
    {
        int warps = (N_NODES + 1) / 2;
        agg128_kernel<<<(warps * 32 + 255) / 256, 256, 0, s0>>>(h2, out, b2);
    }
}

// round 12
// speedup vs baseline: 1.4605x; 1.4605x over previous
#include <cuda_runtime.h>
#include <cuda_fp16.h>
#include <cstdint>

#define N_NODES 50000
#define N_EDGES 800000
#define IN_C 256
#define HID_C 256
#define OUT_C 128
#define NB_SCAN ((N_NODES + 255) / 256)
#define CHUNK0 25088                     // 196 blocks of 128 rows

// ---------------- scratch (static device globals; no runtime alloc) ----------
__device__ __align__(256) __half g_h1[N_NODES * HID_C];
__device__ __align__(256) __half g_a1[N_NODES * HID_C];
__device__ __align__(256) __half g_h2[N_NODES * OUT_C];
__device__ __align__(256) __half g_W1h[HID_C * IN_C];    // W1^T fp16 [N=256][K=256]
__device__ __align__(256) __half g_W2h[OUT_C * HID_C];   // W2^T fp16 [N=128][K=256]
__device__ int2  g_csrw[N_EDGES];        // (src, fp32 bits of dinv[src]) by dst
__device__ int   g_ptr[N_NODES + 1];
__device__ int   g_cnt[N_NODES];
__device__ int   g_cur[N_NODES];
__device__ float g_dinv[N_NODES];
__device__ int   g_bsum[256];
__device__ int   g_is64;

// ---------------- one-time stream/event infra --------------------------------
struct StreamInit {
    cudaStream_t s2;
    cudaEvent_t evF, evJ, evG1, evB;
    StreamInit() {
        cudaStreamCreate(&s2);
        cudaEventCreateWithFlags(&evF, cudaEventDisableTiming);
        cudaEventCreateWithFlags(&evJ, cudaEventDisableTiming);
        cudaEventCreateWithFlags(&evG1, cudaEventDisableTiming);
        cudaEventCreateWithFlags(&evB, cudaEventDisableTiming);
    }
};
static StreamInit g_si;

// ---------------- prep: zero + dtype detect + W2 transpose (fused) -----------
__global__ void prep_kernel(const unsigned int* __restrict__ w,
                            const float* __restrict__ W2,
                            __half* __restrict__ W2T) {
    __shared__ float tbuf[32][33];
    __shared__ int nz;
    int bid = blockIdx.x;
    if (bid < NB_SCAN) {
        int i = bid * 256 + threadIdx.x;
        if (i < N_NODES) { g_cnt[i] = 0; g_cur[i] = 0; }
        if (i == 0) g_ptr[N_NODES] = N_EDGES;
        if (bid == 0) {
            if (threadIdx.x == 0) nz = 0;
            __syncthreads();
            int bad = 0;
            for (int k = threadIdx.x; k < 4096; k += blockDim.x)
                if (w[2 * k + 1] != 0u) bad = 1;
            if (bad) atomicOr(&nz, 1);
            __syncthreads();
            if (threadIdx.x == 0) g_is64 = (nz == 0) ? 1 : 0;
        }
    } else {
        int tb = bid - NB_SCAN;          // 0..31
        int bx = (tb & 3) * 32;          // OUT_C/32 = 4
        int by = (tb >> 2) * 32;         // HID_C/32 = 8
        int x = threadIdx.x & 31, y = threadIdx.x >> 5;
#pragma unroll
        for (int j = 0; j < 32; j += 8)
            tbuf[y + j][x] = W2[(size_t)(by + y + j) * OUT_C + bx + x];
        __syncthreads();
#pragma unroll
        for (int j = 0; j < 32; j += 8)
            W2T[(size_t)(bx + y + j) * HID_C + by + x] = __float2half(tbuf[x][y + j]);
    }
}

__device__ __forceinline__ int edge_at(const void* ei, long long idx) {
    if (g_is64) return (int)((const long long*)ei)[idx];
    return ((const int*)ei)[idx];
}

// ---------------- CSR build --------------------------------------------------
__global__ void count_kernel(const void* __restrict__ ei) {
    int e = blockIdx.x * blockDim.x + threadIdx.x;
    if (e >= N_EDGES) return;
    int c = edge_at(ei, (long long)N_EDGES + e);
    atomicAdd(&g_cnt[c], 1);
}

__global__ void scan1_kernel() {
    int i = blockIdx.x * 256 + threadIdx.x;
    int v = (i < N_NODES) ? g_cnt[i] : 0;
    int lane = threadIdx.x & 31, w = threadIdx.x >> 5;
    for (int o = 16; o; o >>= 1) v += __shfl_down_sync(~0u, v, o);
    __shared__ int ws[8];
    if (!lane) ws[w] = v;
    __syncthreads();
    if (threadIdx.x == 0) {
        int s = 0;
        for (int k = 0; k < 8; k++) s += ws[k];
        g_bsum[blockIdx.x] = s;
    }
}

// merged scan2+scan3: block offset = masked reduction over g_bsum, then local scan
__global__ void scan3m_kernel() {
    int t = threadIdx.x, bid = blockIdx.x;
    int lane = t & 31, w = t >> 5;

    int v = (t < NB_SCAN && t < bid) ? g_bsum[t] : 0;
    for (int o = 16; o; o >>= 1) v += __shfl_down_sync(~0u, v, o);
    __shared__ int ws[8];
    __shared__ int boff;
    if (!lane) ws[w] = v;
    __syncthreads();
    if (t == 0) {
        int s = 0;
        for (int k = 0; k < 8; k++) s += ws[k];
        boff = s;
    }
    __syncthreads();

    int i = bid * 256 + t;
    int c = (i < N_NODES) ? g_cnt[i] : 0;
    int x = c;
    for (int o = 1; o < 32; o <<= 1) {
        int y = __shfl_up_sync(~0u, x, o);
        if (lane >= o) x += y;
    }
    __shared__ int ws2[8], wo[8];
    if (lane == 31) ws2[w] = x;
    __syncthreads();
    if (t == 0) {
        int r = 0;
        for (int k = 0; k < 8; k++) { wo[k] = r; r += ws2[k]; }
    }
    __syncthreads();
    if (i < N_NODES) {
        g_ptr[i] = boff + wo[w] + x - c;
        g_dinv[i] = rsqrtf((float)(c + 1));
    }
}

__global__ void fill_kernel(const void* __restrict__ ei) {
    int e = blockIdx.x * blockDim.x + threadIdx.x;
    if (e >= N_EDGES) return;
    int r = edge_at(ei, e);
    int c = edge_at(ei, (long long)N_EDGES + e);
    int pos = g_ptr[c] + atomicAdd(&g_cur[c], 1);
    g_csrw[pos] = make_int2(r, __float_as_int(g_dinv[r]));
}

// ---------------- W1 transpose+convert ----------------------------------------
__global__ void transpose_h_kernel(const float* __restrict__ W, __half* __restrict__ WT,
                                   int Kd, int Nd) {
    __shared__ float t[32][33];
    int bx = blockIdx.x * 32, by = blockIdx.y * 32;
    int x = threadIdx.x, y = threadIdx.y;
#pragma unroll
    for (int j = 0; j < 32; j += 8)
        t[y + j][x] = W[(size_t)(by + y + j) * Nd + bx + x];
    __syncthreads();
#pragma unroll
    for (int j = 0; j < 32; j += 8)
        WT[(size_t)(bx + y + j) * Kd + by + x] = __float2half(t[x][y + j]);
}

// ---------------- FP16 mma GEMM: C[M,N] = A[M,K] @ Bt[N,K]^T ------------------
// BM=128, BN=64, BK=32. 8 warps as 4(M) x 2(N); warp tile 32x32.
// Register-prefetch pipeline, single SMEM buffer (R10 configuration).
#define BM 128
#define BN 64
#define BK 32

__device__ __forceinline__ void mma_f16(float* c, const uint32_t* a, const uint32_t* b) {
    asm volatile(
        "mma.sync.aligned.m16n8k16.row.col.f32.f16.f16.f32 "
        "{%0,%1,%2,%3}, {%4,%5,%6,%7}, {%8,%9}, {%0,%1,%2,%3};"
        : "+f"(c[0]), "+f"(c[1]), "+f"(c[2]), "+f"(c[3])
        : "r"(a[0]), "r"(a[1]), "r"(a[2]), "r"(a[3]), "r"(b[0]), "r"(b[1]));
}

template <typename TA>
__global__ __launch_bounds__(256) void mma_hgemm_kernel(
    const TA* __restrict__ A, const __half* __restrict__ Bt,
    __half* __restrict__ C, int M, int N, int K)
{
    __shared__ __align__(16) __half As[BM][BK + 8];
    __shared__ __align__(16) __half Bs[BN][BK + 8];

    int tid = threadIdx.x;
    int lane = tid & 31, wid = tid >> 5;
    int wm = (wid & 3) * 32;
    int wn = (wid >> 2) * 32;
    int m0 = blockIdx.x * BM, n0 = blockIdx.y * BN;
    int g = lane >> 2, tq = lane & 3;

    float acc[2][4][4];
#pragma unroll
    for (int mt = 0; mt < 2; mt++)
#pragma unroll
        for (int nt = 0; nt < 4; nt++)
#pragma unroll
            for (int j = 0; j < 4; j++) acc[mt][nt][j] = 0.0f;

    float4 pa_f[4];
    uint4  pa_h[2];
    uint4  pb;

    auto load_tile = [&](int k0) {
        if constexpr (sizeof(TA) == 4) {
#pragma unroll
            for (int i = 0; i < 4; i++) {
                int slot = tid + 256 * i;
                int m = slot >> 3, c4 = slot & 7;
                pa_f[i] = make_float4(0.f, 0.f, 0.f, 0.f);
                if (m0 + m < M)
                    pa_f[i] = *(const float4*)((const float*)A +
                                               (size_t)(m0 + m) * K + k0 + c4 * 4);
            }
        } else {
#pragma unroll
            for (int i = 0; i < 2; i++) {
                int slot = tid + 256 * i;
                int m = slot >> 2, c8 = slot & 3;
                pa_h[i] = make_uint4(0u, 0u, 0u, 0u);
                if (m0 + m < M)
                    pa_h[i] = *(const uint4*)((const __half*)A +
                                              (size_t)(m0 + m) * K + k0 + c8 * 8);
            }
        }
        {
            int n = tid >> 2, c8 = tid & 3;
            pb = *(const uint4*)(Bt + (size_t)(n0 + n) * K + k0 + c8 * 8);
        }
    };

    auto store_tile = [&]() {
        if constexpr (sizeof(TA) == 4) {
#pragma unroll
            for (int i = 0; i < 4; i++) {
                int slot = tid + 256 * i;
                int m = slot >> 3, c4 = slot & 7;
                uint2 u;
                ((__half2*)&u)[0] = __floats2half2_rn(pa_f[i].x, pa_f[i].y);
                ((__half2*)&u)[1] = __floats2half2_rn(pa_f[i].z, pa_f[i].w);
                *(uint2*)&As[m][c4 * 4] = u;
            }
        } else {
#pragma unroll
            for (int i = 0; i < 2; i++) {
                int slot = tid + 256 * i;
                int m = slot >> 2, c8 = slot & 3;
                *(uint4*)&As[m][c8 * 8] = pa_h[i];
            }
        }
        {
            int n = tid >> 2, c8 = tid & 3;
            *(uint4*)&Bs[n][c8 * 8] = pb;
        }
    };

    load_tile(0);
    const int NITER = K / BK;
    for (int it = 0; it < NITER; it++) {
        store_tile();
        __syncthreads();
        if (it + 1 < NITER) load_tile((it + 1) * BK);

#pragma unroll
        for (int kk = 0; kk < BK; kk += 16) {
            uint32_t a[2][4], b[4][2];
#pragma unroll
            for (int mt = 0; mt < 2; mt++) {
                int r = wm + mt * 16 + g;
                a[mt][0] = *(const uint32_t*)&As[r][kk + 2 * tq];
                a[mt][1] = *(const uint32_t*)&As[r + 8][kk + 2 * tq];
                a[mt][2] = *(const uint32_t*)&As[r][kk + 2 * tq + 8];
                a[mt][3] = *(const uint32_t*)&As[r + 8][kk + 2 * tq + 8];
            }
#pragma unroll
            for (int nt = 0; nt < 4; nt++) {
                int n = wn + nt * 8 + g;
                b[nt][0] = *(const uint32_t*)&Bs[n][kk + 2 * tq];
                b[nt][1] = *(const uint32_t*)&Bs[n][kk + 2 * tq + 8];
            }
#pragma unroll
            for (int mt = 0; mt < 2; mt++)
#pragma unroll
                for (int nt = 0; nt < 4; nt++)
                    mma_f16(acc[mt][nt], a[mt], b[nt]);
        }
        __syncthreads();
    }

#pragma unroll
    for (int mt = 0; mt < 2; mt++) {
        int row = m0 + wm + mt * 16 + g;
#pragma unroll
        for (int nt = 0; nt < 4; nt++) {
            int col = n0 + wn + nt * 8 + tq * 2;
            if (row < M)
                *(__half2*)(C + (size_t)row * N + col) =
                    __floats2half2_rn(acc[mt][nt][0], acc[mt][nt][1]);
            if (row + 8 < M)
                *(__half2*)(C + (size_t)(row + 8) * N + col) =
                    __floats2half2_rn(acc[mt][nt][2], acc[mt][nt][3]);
        }
    }
}

// ---------------- aggregation (fp16 features, fp32 accumulate) ---------------
__device__ __forceinline__ void h8_fma(float w, uint4 v, float* acc) {
    const __half2* hp = (const __half2*)&v;
#pragma unroll
    for (int i = 0; i < 4; i++) {
        float2 f = __half22float2(hp[i]);
        acc[2 * i]     += w * f.x;
        acc[2 * i + 1] += w * f.y;
    }
}

__global__ __launch_bounds__(256) void agg256_kernel(
    const __half* __restrict__ h, __half* __restrict__ out,
    const float* __restrict__ bias, int node_base, int node_count)
{
    int warp = (blockIdx.x * blockDim.x + threadIdx.x) >> 5;
    int lane = threadIdx.x & 31;
    if (warp >= node_count) return;
    int node = node_base + warp;

    const uint4* hv = (const uint4*)h;
    int p0 = g_ptr[node], p1 = g_ptr[node + 1];
    float dc = g_dinv[node];

    float acc[8];
#pragma unroll
    for (int j = 0; j < 8; j++) acc[j] = 0.0f;
    h8_fma(dc, hv[(size_t)node * 32 + lane], acc);

    int e = p0;
    for (; e + 4 <= p1; e += 4) {
        int2 c0 = g_csrw[e],     c1 = g_csrw[e + 1];
        int2 c2 = g_csrw[e + 2], c3 = g_csrw[e + 3];
        uint4 v0 = hv[(size_t)c0.x * 32 + lane];
        uint4 v1 = hv[(size_t)c1.x * 32 + lane];
        uint4 v2 = hv[(size_t)c2.x * 32 + lane];
        uint4 v3 = hv[(size_t)c3.x * 32 + lane];
        h8_fma(__int_as_float(c0.y), v0, acc);
        h8_fma(__int_as_float(c1.y), v1, acc);
        h8_fma(__int_as_float(c2.y), v2, acc);
        h8_fma(__int_as_float(c3.y), v3, acc);
    }
    for (; e < p1; e++) {
        int2 c0 = g_csrw[e];
        h8_fma(__int_as_float(c0.y), hv[(size_t)c0.x * 32 + lane], acc);
    }

    float4 b0 = ((const float4*)bias)[lane * 2];
    float4 b1 = ((const float4*)bias)[lane * 2 + 1];
    float r[8];
    r[0] = fmaxf(dc * acc[0] + b0.x, 0.f);
    r[1] = fmaxf(dc * acc[1] + b0.y, 0.f);
    r[2] = fmaxf(dc * acc[2] + b0.z, 0.f);
    r[3] = fmaxf(dc * acc[3] + b0.w, 0.f);
    r[4] = fmaxf(dc * acc[4] + b1.x, 0.f);
    r[5] = fmaxf(dc * acc[5] + b1.y, 0.f);
    r[6] = fmaxf(dc * acc[6] + b1.z, 0.f);
    r[7] = fmaxf(dc * acc[7] + b1.w, 0.f);

    uint4 o;
    __half2* op = (__half2*)&o;
    op[0] = __floats2half2_rn(r[0], r[1]);
    op[1] = __floats2half2_rn(r[2], r[3]);
    op[2] = __floats2half2_rn(r[4], r[5]);
    op[3] = __floats2half2_rn(r[6], r[7]);
    ((uint4*)out)[(size_t)node * 32 + lane] = o;
}

__global__ __launch_bounds__(256) void agg128_kernel(
    const __half* __restrict__ h, float* __restrict__ out,
    const float* __restrict__ bias)
{
    int gwarp = (blockIdx.x * blockDim.x + threadIdx.x) >> 5;
    int lane = threadIdx.x & 31;
    int node = gwarp * 2 + (lane >> 4);
    int l16 = lane & 15;
    if (node >= N_NODES) return;

    const uint4* hv = (const uint4*)h;
    int p0 = g_ptr[node], p1 = g_ptr[node + 1];
    float dc = g_dinv[node];

    float acc[8];
#pragma unroll
    for (int j = 0; j < 8; j++) acc[j] = 0.0f;
    h8_fma(dc, hv[(size_t)node * 16 + l16], acc);

    int e = p0;
    for (; e + 4 <= p1; e += 4) {
        int2 c0 = g_csrw[e],     c1 = g_csrw[e + 1];
        int2 c2 = g_csrw[e + 2], c3 = g_csrw[e + 3];
        uint4 v0 = hv[(size_t)c0.x * 16 + l16];
        uint4 v1 = hv[(size_t)c1.x * 16 + l16];
        uint4 v2 = hv[(size_t)c2.x * 16 + l16];
        uint4 v3 = hv[(size_t)c3.x * 16 + l16];
        h8_fma(__int_as_float(c0.y), v0, acc);
        h8_fma(__int_as_float(c1.y), v1, acc);
        h8_fma(__int_as_float(c2.y), v2, acc);
        h8_fma(__int_as_float(c3.y), v3, acc);
    }
    for (; e < p1; e++) {
        int2 c0 = g_csrw[e];
        h8_fma(__int_as_float(c0.y), hv[(size_t)c0.x * 16 + l16], acc);
    }

    float4 b0 = ((const float4*)bias)[l16 * 2];
    float4 b1 = ((const float4*)bias)[l16 * 2 + 1];
    float4 o0, o1;
    o0.x = dc * acc[0] + b0.x;
    o0.y = dc * acc[1] + b0.y;
    o0.z = dc * acc[2] + b0.z;
    o0.w = dc * acc[3] + b0.w;
    o1.x = dc * acc[4] + b1.x;
    o1.y = dc * acc[5] + b1.y;
    o1.z = dc * acc[6] + b1.z;
    o1.w = dc * acc[7] + b1.w;

    float4* ov = (float4*)(out + (size_t)node * 128 + l16 * 8);
    ov[0] = o0;
    ov[1] = o1;
}

// ---------------- launch ------------------------------------------------------
extern "C" void kernel_launch(void* const* d_in, const int* in_sizes, int n_in,
                              void* d_out, int out_size)
{
    const float* x  = (const float*)d_in[0];
    const void*  ei = d_in[1];
    const float* W1 = (const float*)d_in[2];
    const float* b1 = (const float*)d_in[3];
    const float* W2 = (const float*)d_in[4];
    const float* b2 = (const float*)d_in[5];
    float* out = (float*)d_out;

    __half* h1;  cudaGetSymbolAddress((void**)&h1, g_h1);
    __half* a1;  cudaGetSymbolAddress((void**)&a1, g_a1);
    __half* h2;  cudaGetSymbolAddress((void**)&h2, g_h2);
    __half* w1h; cudaGetSymbolAddress((void**)&w1h, g_W1h);
    __half* w2h; cudaGetSymbolAddress((void**)&w2h, g_W2h);

    cudaStream_t s0 = 0, s2 = g_si.s2;

    // ---- fork ----
    cudaEventRecord(g_si.evF, s0);
    cudaStreamWaitEvent(s2, g_si.evF, 0);

    // branch A (s2): fused prep (zero+detect+W2T) + CSR build (5 launches)
    prep_kernel<<<NB_SCAN + 32, 256, 0, s2>>>((const unsigned int*)ei, W2, w2h);
    count_kernel<<<(N_EDGES + 255) / 256, 256, 0, s2>>>(ei);
    scan1_kernel<<<NB_SCAN, 256, 0, s2>>>();
    scan3m_kernel<<<NB_SCAN, 256, 0, s2>>>();
    fill_kernel<<<(N_EDGES + 255) / 256, 256, 0, s2>>>(ei);
    cudaEventRecord(g_si.evJ, s2);

    // branch B (s0): W1 prep + GEMM1 (fp16)
    transpose_h_kernel<<<dim3(HID_C / 32, IN_C / 32), dim3(32, 8), 0, s0>>>(
        W1, w1h, IN_C, HID_C);
    int grid_m = (N_NODES + BM - 1) / BM;   // 391
    mma_hgemm_kernel<float><<<dim3(grid_m, HID_C / BN), 256, 0, s0>>>(
        x, w1h, h1, N_NODES, HID_C, IN_C);
    cudaEventRecord(g_si.evG1, s0);

    // ---- pipelined layer-1 agg + layer-2 GEMM in two row chunks ----
    const int c1n = N_NODES - CHUNK0;                 // 24912
    // s0: chunk0
    cudaStreamWaitEvent(s0, g_si.evJ, 0);
    agg256_kernel<<<(CHUNK0 * 32 + 255) / 256, 256, 0, s0>>>(h1, a1, b1, 0, CHUNK0);
    mma_hgemm_kernel<__half><<<dim3(CHUNK0 / BM, OUT_C / BN), 256, 0, s0>>>(
        a1, w2h, h2, CHUNK0, OUT_C, HID_C);
    // s2: chunk1
    cudaStreamWaitEvent(s2, g_si.evG1, 0);
    agg256_kernel<<<(c1n * 32 + 255) / 256, 256, 0, s2>>>(h1, a1, b1, CHUNK0, c1n);
    mma_hgemm_kernel<__half><<<dim3((c1n + BM - 1) / BM, OUT_C / BN), 256, 0, s2>>>(
        a1 + (size_t)CHUNK0 * HID_C, w2h, h2 + (size_t)CHUNK0 * OUT_C,
        c1n, OUT_C, HID_C);
    cudaEventRecord(g_si.evB, s2);

    // ---- join + final aggregation ----
    cudaStreamWaitEvent(s0, g_si.evB, 0);
    {
        int warps = (N_NODES + 1) / 2;
        agg128_kernel<<<(warps * 32 + 255) / 256, 256, 0, s0>>>(h2, out, b2);
    }
}